// round 9
// baseline (speedup 1.0000x reference)
#include <cuda_runtime.h>
#include <cuda_bf16.h>
#include <cstdint>

#define NB    256
#define NC    512
#define NHW   81
#define NFLAT (NC*NHW)           // 41472 per batch
#define EPSV  1e-5f

__device__ __forceinline__ float to_tf32(float x) {
    float r; asm("cvt.rna.tf32.f32 %0, %1;" : "=f"(r) : "f"(x)); return r;
}
// m16n8k8 tf32 warp MMA (baseline PTX, sm_80+): D += A*B
__device__ __forceinline__ void mma_tf32(float c[4],
                                         uint32_t a0, uint32_t a1,
                                         uint32_t a2, uint32_t a3,
                                         uint32_t b0, uint32_t b1) {
    asm volatile("mma.sync.aligned.m16n8k8.row.col.f32.tf32.tf32.f32 "
                 "{%0,%1,%2,%3}, {%4,%5,%6,%7}, {%8,%9}, {%0,%1,%2,%3};"
                 : "+f"(c[0]), "+f"(c[1]), "+f"(c[2]), "+f"(c[3])
                 : "r"(a0), "r"(a1), "r"(a2), "r"(a3), "r"(b0), "r"(b1));
}
__device__ __forceinline__ void cp_async16(uint32_t s, const void* g) {
    asm volatile("cp.async.ca.shared.global [%0], [%1], 16;" :: "r"(s), "l"(g));
}
__device__ __forceinline__ void cp_commit() {
    asm volatile("cp.async.commit_group;");
}
template<int N>
__device__ __forceinline__ void cp_wait() {
    asm volatile("cp.async.wait_group %0;" :: "n"(N));
}

// Global scratch (allocation-free rule: __device__ arrays)
__device__ __align__(16) float g_k1[(size_t)NB * NFLAT];  // SeMCA key
__device__ __align__(16) float g_v [(size_t)NB * NFLAT];  // SeMCA value (dw3x3)

// ---------------------------------------------------------------------------
// Kernel A (banded): unchanged (passing since round 5).
// ---------------------------------------------------------------------------
#define A_SMEM_FLOATS (5832 + 729 + 81 + 8*1296)   // 17010

__global__ __launch_bounds__(256, 3)
void dmuca_kernelA(const float* __restrict__ x,
                   const float* __restrict__ alpha_p,
                   const float* __restrict__ sa_key_w,
                   const float* __restrict__ sa_key_bn,
                   const float* __restrict__ sa_att_w1,
                   const float* __restrict__ sa_att_bn,
                   const float* __restrict__ sa_att_w2,
                   const float* __restrict__ sa_att_b2,
                   const float* __restrict__ se_key_w,
                   const float* __restrict__ se_key_b,
                   const float* __restrict__ se_val_w,
                   const float* __restrict__ se_val_b,
                   float* __restrict__ out)
{
    extern __shared__ float sm[];
    float* Xs    = sm;
    float* sekw  = sm + 5832;
    float* sekb  = sekw + 729;
    float* stage = sekb + 81;

    const int bb   = blockIdx.x;
    const int b    = bb >> 3;
    const int band = bb & 7;
    const int chlo = band << 6;
    const int tid  = threadIdx.x;
    const int warp = tid >> 5;
    const int lane = tid & 31;
    const float* xb = x + (size_t)b * NFLAT;

    {
        const int gbase = (chlo - 4) * NHW;
        for (int i = tid; i < 5832; i += 256) {
            const int g = gbase + i;
            Xs[i] = ((unsigned)g < (unsigned)NFLAT) ? xb[g] : 0.f;
        }
        for (int i = tid; i < 729; i += 256) sekw[i] = se_key_w[i];
        if (tid < 81) sekb[tid] = se_key_b[tid];
    }
    __syncthreads();

    const float alpha = alpha_p[0];
    const float oma   = 1.0f - alpha;

    const int g_head = (chlo >> 3) + warp;
    const int chbase = chlo + warp * 8;
    float* ks   = stage + warp * 1296;
    float* k1st = ks + 648;

    #pragma unroll
    for (int l = 0; l < 8; l++) {
        const int ch = chbase + l;
        const int lr = warp*8 + l + 4;
        const float* Xc = Xs + lr * NHW;
        float wkv[9], wks[9];
        #pragma unroll
        for (int k = 0; k < 9; k++) wkv[k] = __ldg(se_val_w + ch*9 + k);
        #pragma unroll
        for (int k = 0; k < 9; k++) wks[k] = __ldg(sa_key_w + ch*9 + k);
        const float vbias = __ldg(se_val_b + ch);
        const float gam = __ldg(sa_key_bn + ch);
        const float bet = __ldg(sa_key_bn + 512 + ch);
        const float mea = __ldg(sa_key_bn + 1024 + ch);
        const float var = __ldg(sa_key_bn + 1536 + ch);
        const float s   = gam * rsqrtf(var + EPSV);
        const float sh  = bet - mea * s;

        float* gk = g_k1 + (size_t)b * NFLAT + ch * NHW;
        float* gv = g_v  + (size_t)b * NFLAT + ch * NHW;

        #pragma unroll
        for (int t = 0; t < 3; t++) {
            const int p = lane + 32 * t;
            if (p < 81) {
                float acc = sekb[p];
                #pragma unroll
                for (int d = 0; d < 9; d++)
                    acc = fmaf(sekw[p*9 + d], Xs[(lr - 4 + d)*NHW + p], acc);
                gk[p] = acc;
                k1st[l*81 + p] = acc;

                const int h = p / 9, w = p - h * 9;
                float va = vbias, sa = 0.f;
                #pragma unroll
                for (int kh = 0; kh < 3; kh++) {
                    const int hh = h + kh - 1;
                    if ((unsigned)hh < 9u) {
                        #pragma unroll
                        for (int kw = 0; kw < 3; kw++) {
                            const int ww = w + kw - 1;
                            if ((unsigned)ww < 9u) {
                                const float xv = Xc[hh*9 + ww];
                                va = fmaf(wkv[kh*3+kw], xv, va);
                                sa = fmaf(wks[kh*3+kw], xv, sa);
                            }
                        }
                    }
                }
                gv[p] = va;
                ks[l*81 + p] = fmaxf(fmaf(sa, s, sh), 0.f);
            }
        }
    }
    __syncwarp();

    const float bg = __ldg(sa_att_b2 + g_head);
    float a2b[3] = {bg, bg, bg};
    #pragma unroll
    for (int o = 0; o < 8; o++) {
        const int oc = chbase + o;
        float w1r[16];
        #pragma unroll
        for (int i = 0; i < 16; i++) w1r[i] = __ldg(sa_att_w1 + oc*16 + i);
        const float gam = __ldg(sa_att_bn + oc);
        const float bet = __ldg(sa_att_bn + 512 + oc);
        const float mea = __ldg(sa_att_bn + 1024 + oc);
        const float var = __ldg(sa_att_bn + 1536 + oc);
        const float s2  = gam * rsqrtf(var + EPSV);
        const float sh2 = bet - mea * s2;
        const float w2v = __ldg(sa_att_w2 + oc);
        #pragma unroll
        for (int t = 0; t < 3; t++) {
            const int pp = lane + 32 * t;
            if (pp < 81) {
                float aa = 0.f;
                #pragma unroll
                for (int l = 0; l < 8; l++) {
                    aa = fmaf(w1r[2*l],   ks[l*81 + pp], aa);
                    aa = fmaf(w1r[2*l+1], Xs[(warp*8 + l + 4)*NHW + pp], aa);
                }
                aa = fmaxf(fmaf(aa, s2, sh2), 0.f);
                a2b[t] = fmaf(w2v, aa, a2b[t]);
            }
        }
    }

    float m = -1e30f;
    #pragma unroll
    for (int t = 0; t < 3; t++) { if (lane + 32*t < 81) m = fmaxf(m, a2b[t]); }
    #pragma unroll
    for (int off = 16; off > 0; off >>= 1)
        m = fmaxf(m, __shfl_xor_sync(0xffffffffu, m, off));
    float ex[3] = {0.f, 0.f, 0.f};
    float ssum = 0.f;
    #pragma unroll
    for (int t = 0; t < 3; t++) {
        const int pp = lane + 32 * t;
        if (pp < 81) { ex[t] = __expf(a2b[t] - m); ssum += ex[t]; }
    }
    #pragma unroll
    for (int off = 16; off > 0; off >>= 1)
        ssum += __shfl_xor_sync(0xffffffffu, ssum, off);
    const float inv = 1.0f / ssum;

    #pragma unroll
    for (int t = 0; t < 3; t++) {
        const int pp = lane + 32 * t;
        if (pp < 81) {
            const float att = ex[t] * inv;
            #pragma unroll
            for (int l = 0; l < 8; l++) {
                const int ch = chbase + l;
                const float o2 = ks[l*81 + pp]
                               + att * Xs[(warp*8 + l + 4)*NHW + pp];
                out[(size_t)b * NFLAT + ch*NHW + pp]
                    = oma * o2 + alpha * k1st[l*81 + pp];
            }
        }
    }
}

// ---------------------------------------------------------------------------
// Kernel B (warp-MMA tf32, fused passes): grid = NB*2, 256 threads, 2 CTAs/SM.
// Per CTA: 256 cols of C^T[512,88] = S^T[512,176] @ W1^T[176,88].
// S chunks staged untransposed [k=16][n=256 (stride 264)] via cp.async
// (double buffered); W1f [k=176][o=88] tf32 staged once. Both m-passes share
// each staged chunk and each W1 fragment. Single tf32 (no hi/lo split).
// Epilogue: bn+relu+w2 in registers -> a2s logits -> softmax -> v-band smem
// -> out += alpha * window-combine.
//
// smem floats: SH[2*16*264=8448]@0 | W1f[176*88=15488]@8448 (ends 23936)
//   vsm alias @0 (264*81=21384) | a2s@23936 (2304) | w2s@26240 (729)
//   bnS@26969 (81) | bnH@27050 (81)  -> total 27131 fl = 108524 B
// ---------------------------------------------------------------------------
#define FB_SH   0
#define FB_W1F  8448
#define FB_A2S  23936
#define FB_W2   26240
#define FB_BNS  26969
#define FB_BNH  27050
#define B_SMEM_FLOATS 27131
#define SH_STRIDE 264
#define W1_STRIDE 88

__global__ __launch_bounds__(256, 2)
void dmuca_kernelB(const float* __restrict__ x,
                   const float* __restrict__ alpha_p,
                   const float* __restrict__ se_att_w1,
                   const float* __restrict__ se_att_bn,
                   const float* __restrict__ se_att_w2,
                   const float* __restrict__ se_att_b2,
                   float* __restrict__ out)
{
    extern __shared__ float sm[];
    float* SH  = sm + FB_SH;     // 2 buffers of [16][264]
    float* W1f = sm + FB_W1F;    // [176][88] tf32
    float* vsm = sm;             // epilogue alias 264*81
    float* a2s = sm + FB_A2S;    // [9][256]
    float* w2s = sm + FB_W2;
    float* bnS = sm + FB_BNS;
    float* bnH = sm + FB_BNH;

    const int bx   = blockIdx.x;
    const int b    = bx >> 1;
    const int hf   = bx & 1;
    const int cbase = hf << 8;   // 0 or 256
    const int tid  = threadIdx.x;
    const int warp = tid >> 5;   // 0..7
    const int lane = tid & 31;
    const int gid  = lane >> 2;  // 0..7
    const int tig  = lane & 3;   // 0..3
    const float* xb  = x    + (size_t)b * NFLAT;
    const float* k1b = g_k1 + (size_t)b * NFLAT;

    const uint32_t sh_base = (uint32_t)__cvta_generic_to_shared(SH);

    // one-time staging: W1f (tf32, zero-padded), w2s, bn scale/shift
    for (int i = tid; i < 176*W1_STRIDE; i += 256) {
        const int k = i / W1_STRIDE, o = i - k * W1_STRIDE;
        const float w = (o < 81 && k < 162) ? __ldg(se_att_w1 + o*162 + k) : 0.f;
        W1f[i] = to_tf32(w);
    }
    for (int i = tid; i < 729; i += 256) w2s[i] = se_att_w2[i];
    if (tid < 81) {
        const float gam = se_att_bn[tid],       bet = se_att_bn[81 + tid];
        const float mea = se_att_bn[162 + tid], var = se_att_bn[243 + tid];
        const float s = gam * rsqrtf(var + EPSV);
        bnS[tid] = s; bnH[tid] = bet - mea * s;
    }

    // chunk stager: chunk c (k rows c*16..c*16+15), 256 n-cols, cp.async
    auto stage_chunk = [&](int c, int buf) {
        const uint32_t boff = (uint32_t)(buf * 16 * SH_STRIDE * 4);
        #pragma unroll
        for (int q = 0; q < 4; q++) {
            const int f4 = q * 256 + tid;          // 0..1023
            const int kk = f4 >> 6, c4 = f4 & 63;  // 64 float4 per 256-f row
            const int j  = c * 16 + kk;
            const uint32_t dst = sh_base + boff
                               + (uint32_t)((kk * SH_STRIDE + c4 * 4) * 4);
            if (j < 81) {
                cp_async16(dst, (const void*)(xb + j*512 + cbase + c4*4));
            } else if (j < 162) {
                cp_async16(dst, (const void*)(k1b + (j-81)*512 + cbase + c4*4));
            } else {
                float4 z = {0.f, 0.f, 0.f, 0.f};
                *(float4*)(SH + buf*16*SH_STRIDE + kk*SH_STRIDE + c4*4) = z;
            }
        }
        cp_commit();
    };

    float acc[2][11][4];
    #pragma unroll
    for (int p = 0; p < 2; p++)
        #pragma unroll
        for (int nb = 0; nb < 11; nb++)
            #pragma unroll
            for (int e = 0; e < 4; e++) acc[p][nb][e] = 0.f;

    stage_chunk(0, 0);

    for (int kc = 0; kc < 11; kc++) {
        if (kc < 10) { stage_chunk(kc + 1, (kc + 1) & 1); cp_wait<1>(); }
        else         { cp_wait<0>(); }
        __syncthreads();

        const float* sb = SH + (kc & 1) * 16 * SH_STRIDE;
        #pragma unroll
        for (int ks = 0; ks < 2; ks++) {
            const float* r0 = sb + (ks*8 + tig)     * SH_STRIDE;
            const float* r4 = sb + (ks*8 + tig + 4) * SH_STRIDE;
            uint32_t af[2][4];
            #pragma unroll
            for (int p = 0; p < 2; p++) {
                const int m0 = (warp + 8*p) * 16;
                af[p][0] = __float_as_uint(r0[m0 + gid]);
                af[p][1] = __float_as_uint(r0[m0 + gid + 8]);
                af[p][2] = __float_as_uint(r4[m0 + gid]);
                af[p][3] = __float_as_uint(r4[m0 + gid + 8]);
            }
            const int jr = kc*16 + ks*8 + tig;
            const float* w0 = W1f + (size_t)jr * W1_STRIDE;
            const float* w4 = W1f + (size_t)(jr + 4) * W1_STRIDE;
            #pragma unroll
            for (int nb = 0; nb < 11; nb++) {
                const uint32_t b0 = __float_as_uint(w0[nb*8 + gid]);
                const uint32_t b1 = __float_as_uint(w4[nb*8 + gid]);
                mma_tf32(acc[0][nb], af[0][0], af[0][1], af[0][2], af[0][3], b0, b1);
                mma_tf32(acc[1][nb], af[1][0], af[1][1], af[1][2], af[1][3], b0, b1);
            }
        }
        __syncthreads();
    }

    // register epilogue: bn+relu+w2 -> logits; one pass at a time
    #pragma unroll
    for (int p = 0; p < 2; p++) {
        float lg[2][9];
        #pragma unroll
        for (int rr = 0; rr < 2; rr++)
            #pragma unroll
            for (int d = 0; d < 9; d++) lg[rr][d] = 0.f;
        #pragma unroll
        for (int nb = 0; nb < 11; nb++) {
            #pragma unroll
            for (int e = 0; e < 4; e++) {
                const int o = nb*8 + tig*2 + (e & 1);
                if (o < 81) {
                    const float a1 = fmaxf(fmaf(acc[p][nb][e], bnS[o], bnH[o]), 0.f);
                    const int rr = e >> 1;
                    #pragma unroll
                    for (int d = 0; d < 9; d++)
                        lg[rr][d] = fmaf(w2s[d*81 + o], a1, lg[rr][d]);
                }
            }
        }
        #pragma unroll
        for (int rr = 0; rr < 2; rr++)
            #pragma unroll
            for (int d = 0; d < 9; d++) {
                lg[rr][d] += __shfl_xor_sync(0xffffffffu, lg[rr][d], 1);
                lg[rr][d] += __shfl_xor_sync(0xffffffffu, lg[rr][d], 2);
            }
        if (tig == 0) {
            const int m0 = (warp + 8*p) * 16;
            #pragma unroll
            for (int d = 0; d < 9; d++) {
                const float bias = __ldg(se_att_b2 + d);
                a2s[d*256 + m0 + gid]     = lg[0][d] + bias;
                a2s[d*256 + m0 + gid + 8] = lg[1][d] + bias;
            }
        }
    }
    __syncthreads();

    // softmax over the 9 spectral taps, per column
    {
        const int n = tid;
        float v[9], mx = -1e30f;
        #pragma unroll
        for (int d = 0; d < 9; d++) { v[d] = a2s[d*256 + n]; mx = fmaxf(mx, v[d]); }
        float ssum = 0.f;
        #pragma unroll
        for (int d = 0; d < 9; d++) { v[d] = __expf(v[d] - mx); ssum += v[d]; }
        const float inv = 1.0f / ssum;
        #pragma unroll
        for (int d = 0; d < 9; d++) a2s[d*256 + n] = v[d] * inv;
    }
    __syncthreads();    // GEMM smem reads done; safe to overwrite with vsm

    // stage v band (channels cbase-4 .. cbase+259, zero-filled at edges)
    {
        const float* vb = g_v + (size_t)b * NFLAT;
        const int gbase = (cbase - 4) * NHW;
        for (int i = tid; i < 264 * NHW; i += 256) {
            const int g = gbase + i;
            vsm[i] = ((unsigned)g < (unsigned)NFLAT) ? vb[g] : 0.f;
        }
    }
    __syncthreads();

    // out += alpha * sum_d attn[d,ch] * v[ch+d-4, p]; warp owns 32 channels
    const float alpha = alpha_p[0];
    float* outb = out + (size_t)b * NFLAT + (size_t)cbase * NHW;
    for (int ci = 0; ci < 32; ci++) {
        const int chl = warp * 32 + ci;
        float at[9];
        #pragma unroll
        for (int d = 0; d < 9; d++) at[d] = a2s[d*256 + chl];   // broadcast
        #pragma unroll
        for (int t = 0; t < 3; t++) {
            const int p = lane + 32 * t;
            if (p < 81) {
                float s = 0.f;
                #pragma unroll
                for (int d = 0; d < 9; d++)
                    s = fmaf(at[d], vsm[(chl + d)*81 + p], s);
                outb[chl*81 + p] += alpha * s;
            }
        }
    }
}

extern "C" void kernel_launch(void* const* d_in, const int* in_sizes, int n_in,
                              void* d_out, int out_size) {
    const float* x         = (const float*)d_in[0];
    const float* alpha     = (const float*)d_in[1];
    const float* sa_key_w  = (const float*)d_in[2];
    const float* sa_key_bn = (const float*)d_in[3];
    const float* sa_att_w1 = (const float*)d_in[4];
    const float* sa_att_bn = (const float*)d_in[5];
    const float* sa_att_w2 = (const float*)d_in[6];
    const float* sa_att_b2 = (const float*)d_in[7];
    const float* se_key_w  = (const float*)d_in[8];
    const float* se_key_b  = (const float*)d_in[9];
    const float* se_att_w1 = (const float*)d_in[10];
    const float* se_att_bn = (const float*)d_in[11];
    const float* se_att_w2 = (const float*)d_in[12];
    const float* se_att_b2 = (const float*)d_in[13];
    const float* se_val_w  = (const float*)d_in[14];
    const float* se_val_b  = (const float*)d_in[15];
    float* out = (float*)d_out;

    const int smemA = A_SMEM_FLOATS * 4;     // 68040 B
    const int smemB = B_SMEM_FLOATS * 4;     // 108524 B
    cudaFuncSetAttribute(dmuca_kernelA,
        cudaFuncAttributeMaxDynamicSharedMemorySize, smemA);
    cudaFuncSetAttribute(dmuca_kernelB,
        cudaFuncAttributeMaxDynamicSharedMemorySize, smemB);

    dmuca_kernelA<<<NB*8, 256, smemA>>>(x, alpha, sa_key_w, sa_key_bn,
                                        sa_att_w1, sa_att_bn, sa_att_w2, sa_att_b2,
                                        se_key_w, se_key_b, se_val_w, se_val_b, out);
    dmuca_kernelB<<<NB*2, 256, smemB>>>(x, alpha, se_att_w1, se_att_bn,
                                        se_att_w2, se_att_b2, out);
}

// round 10
// speedup vs baseline: 1.2533x; 1.2533x over previous
#include <cuda_runtime.h>
#include <cuda_bf16.h>
#include <cstdint>

#define NB    256
#define NC    512
#define NHW   81
#define NFLAT (NC*NHW)           // 41472 per batch
#define EPSV  1e-5f

__device__ __forceinline__ float to_tf32(float x) {
    float r; asm("cvt.rna.tf32.f32 %0, %1;" : "=f"(r) : "f"(x)); return r;
}
// m16n8k8 tf32 warp MMA (baseline PTX, sm_80+): D += A*B
__device__ __forceinline__ void mma_tf32(float c[4],
                                         uint32_t a0, uint32_t a1,
                                         uint32_t a2, uint32_t a3,
                                         uint32_t b0, uint32_t b1) {
    asm volatile("mma.sync.aligned.m16n8k8.row.col.f32.tf32.tf32.f32 "
                 "{%0,%1,%2,%3}, {%4,%5,%6,%7}, {%8,%9}, {%0,%1,%2,%3};"
                 : "+f"(c[0]), "+f"(c[1]), "+f"(c[2]), "+f"(c[3])
                 : "r"(a0), "r"(a1), "r"(a2), "r"(a3), "r"(b0), "r"(b1));
}

// Global scratch (allocation-free rule: __device__ arrays)
__device__ __align__(16) float g_k1[(size_t)NB * NFLAT];  // SeMCA key
__device__ __align__(16) float g_v [(size_t)NB * NFLAT];  // SeMCA value (dw3x3)

// ---------------------------------------------------------------------------
// Kernel A (banded): unchanged (passing since round 5).
// ---------------------------------------------------------------------------
#define A_SMEM_FLOATS (5832 + 729 + 81 + 8*1296)   // 17010

__global__ __launch_bounds__(256, 3)
void dmuca_kernelA(const float* __restrict__ x,
                   const float* __restrict__ alpha_p,
                   const float* __restrict__ sa_key_w,
                   const float* __restrict__ sa_key_bn,
                   const float* __restrict__ sa_att_w1,
                   const float* __restrict__ sa_att_bn,
                   const float* __restrict__ sa_att_w2,
                   const float* __restrict__ sa_att_b2,
                   const float* __restrict__ se_key_w,
                   const float* __restrict__ se_key_b,
                   const float* __restrict__ se_val_w,
                   const float* __restrict__ se_val_b,
                   float* __restrict__ out)
{
    extern __shared__ float sm[];
    float* Xs    = sm;
    float* sekw  = sm + 5832;
    float* sekb  = sekw + 729;
    float* stage = sekb + 81;

    const int bb   = blockIdx.x;
    const int b    = bb >> 3;
    const int band = bb & 7;
    const int chlo = band << 6;
    const int tid  = threadIdx.x;
    const int warp = tid >> 5;
    const int lane = tid & 31;
    const float* xb = x + (size_t)b * NFLAT;

    {
        const int gbase = (chlo - 4) * NHW;
        for (int i = tid; i < 5832; i += 256) {
            const int g = gbase + i;
            Xs[i] = ((unsigned)g < (unsigned)NFLAT) ? xb[g] : 0.f;
        }
        for (int i = tid; i < 729; i += 256) sekw[i] = se_key_w[i];
        if (tid < 81) sekb[tid] = se_key_b[tid];
    }
    __syncthreads();

    const float alpha = alpha_p[0];
    const float oma   = 1.0f - alpha;

    const int g_head = (chlo >> 3) + warp;
    const int chbase = chlo + warp * 8;
    float* ks   = stage + warp * 1296;
    float* k1st = ks + 648;

    #pragma unroll
    for (int l = 0; l < 8; l++) {
        const int ch = chbase + l;
        const int lr = warp*8 + l + 4;
        const float* Xc = Xs + lr * NHW;
        float wkv[9], wks[9];
        #pragma unroll
        for (int k = 0; k < 9; k++) wkv[k] = __ldg(se_val_w + ch*9 + k);
        #pragma unroll
        for (int k = 0; k < 9; k++) wks[k] = __ldg(sa_key_w + ch*9 + k);
        const float vbias = __ldg(se_val_b + ch);
        const float gam = __ldg(sa_key_bn + ch);
        const float bet = __ldg(sa_key_bn + 512 + ch);
        const float mea = __ldg(sa_key_bn + 1024 + ch);
        const float var = __ldg(sa_key_bn + 1536 + ch);
        const float s   = gam * rsqrtf(var + EPSV);
        const float sh  = bet - mea * s;

        float* gk = g_k1 + (size_t)b * NFLAT + ch * NHW;
        float* gv = g_v  + (size_t)b * NFLAT + ch * NHW;

        #pragma unroll
        for (int t = 0; t < 3; t++) {
            const int p = lane + 32 * t;
            if (p < 81) {
                float acc = sekb[p];
                #pragma unroll
                for (int d = 0; d < 9; d++)
                    acc = fmaf(sekw[p*9 + d], Xs[(lr - 4 + d)*NHW + p], acc);
                gk[p] = acc;
                k1st[l*81 + p] = acc;

                const int h = p / 9, w = p - h * 9;
                float va = vbias, sa = 0.f;
                #pragma unroll
                for (int kh = 0; kh < 3; kh++) {
                    const int hh = h + kh - 1;
                    if ((unsigned)hh < 9u) {
                        #pragma unroll
                        for (int kw = 0; kw < 3; kw++) {
                            const int ww = w + kw - 1;
                            if ((unsigned)ww < 9u) {
                                const float xv = Xc[hh*9 + ww];
                                va = fmaf(wkv[kh*3+kw], xv, va);
                                sa = fmaf(wks[kh*3+kw], xv, sa);
                            }
                        }
                    }
                }
                gv[p] = va;
                ks[l*81 + p] = fmaxf(fmaf(sa, s, sh), 0.f);
            }
        }
    }
    __syncwarp();

    const float bg = __ldg(sa_att_b2 + g_head);
    float a2b[3] = {bg, bg, bg};
    #pragma unroll
    for (int o = 0; o < 8; o++) {
        const int oc = chbase + o;
        float w1r[16];
        #pragma unroll
        for (int i = 0; i < 16; i++) w1r[i] = __ldg(sa_att_w1 + oc*16 + i);
        const float gam = __ldg(sa_att_bn + oc);
        const float bet = __ldg(sa_att_bn + 512 + oc);
        const float mea = __ldg(sa_att_bn + 1024 + oc);
        const float var = __ldg(sa_att_bn + 1536 + oc);
        const float s2  = gam * rsqrtf(var + EPSV);
        const float sh2 = bet - mea * s2;
        const float w2v = __ldg(sa_att_w2 + oc);
        #pragma unroll
        for (int t = 0; t < 3; t++) {
            const int pp = lane + 32 * t;
            if (pp < 81) {
                float aa = 0.f;
                #pragma unroll
                for (int l = 0; l < 8; l++) {
                    aa = fmaf(w1r[2*l],   ks[l*81 + pp], aa);
                    aa = fmaf(w1r[2*l+1], Xs[(warp*8 + l + 4)*NHW + pp], aa);
                }
                aa = fmaxf(fmaf(aa, s2, sh2), 0.f);
                a2b[t] = fmaf(w2v, aa, a2b[t]);
            }
        }
    }

    float m = -1e30f;
    #pragma unroll
    for (int t = 0; t < 3; t++) { if (lane + 32*t < 81) m = fmaxf(m, a2b[t]); }
    #pragma unroll
    for (int off = 16; off > 0; off >>= 1)
        m = fmaxf(m, __shfl_xor_sync(0xffffffffu, m, off));
    float ex[3] = {0.f, 0.f, 0.f};
    float ssum = 0.f;
    #pragma unroll
    for (int t = 0; t < 3; t++) {
        const int pp = lane + 32 * t;
        if (pp < 81) { ex[t] = __expf(a2b[t] - m); ssum += ex[t]; }
    }
    #pragma unroll
    for (int off = 16; off > 0; off >>= 1)
        ssum += __shfl_xor_sync(0xffffffffu, ssum, off);
    const float inv = 1.0f / ssum;

    #pragma unroll
    for (int t = 0; t < 3; t++) {
        const int pp = lane + 32 * t;
        if (pp < 81) {
            const float att = ex[t] * inv;
            #pragma unroll
            for (int l = 0; l < 8; l++) {
                const int ch = chbase + l;
                const float o2 = ks[l*81 + pp]
                               + att * Xs[(warp*8 + l + 4)*NHW + pp];
                out[(size_t)b * NFLAT + ch*NHW + pp]
                    = oma * o2 + alpha * k1st[l*81 + pp];
            }
        }
    }
}

// ---------------------------------------------------------------------------
// Kernel B (warp-MMA tf32, single precision path): grid = NB, 512 threads.
// C^T[512,88] = S^T[512,176] @ W1^T[176,88]; S = [x rows 0..80 | k1 81..161].
// Round-8 structure; hi/lo split removed (round 9 validated single tf32:
// rel_err 1.6e-5). 2 passes: warp owns m16 x n88; logits (bn+relu+w2) folded
// into the register epilogue with a 4-lane shfl reduce. Softmax + v-band + out.
//
// smem floats: SH[512*17]@0 | W1f[176*104]@17408 (ends 35712)
//              vsm alias @0 (520*81=42120) | a2s@42120 (4608) | w2s@46728 (729)
//              bnS@47457 (81) | bnH@47538 (81)   total 47619 fl = 190476 B
// ---------------------------------------------------------------------------
#define FB_SH   0
#define FB_W1F  17408
#define FB_A2S  42120
#define FB_W2   46728
#define FB_BNS  47457
#define FB_BNH  47538
#define B_SMEM_FLOATS 47619

__global__ __launch_bounds__(512, 1)
void dmuca_kernelB(const float* __restrict__ x,
                   const float* __restrict__ alpha_p,
                   const float* __restrict__ se_att_w1,
                   const float* __restrict__ se_att_bn,
                   const float* __restrict__ se_att_w2,
                   const float* __restrict__ se_att_b2,
                   float* __restrict__ out)
{
    extern __shared__ float sm[];
    float* SH  = sm + FB_SH;    // [n=512][k=16] stride 17, tf32 of S^T
    float* W1f = sm + FB_W1F;   // [j=176][o=104] stride 104, tf32
    float* vsm = sm;            // epilogue alias, 520*81
    float* a2s = sm + FB_A2S;
    float* w2s = sm + FB_W2;
    float* bnS = sm + FB_BNS;
    float* bnH = sm + FB_BNH;

    const int b    = blockIdx.x;
    const int tid  = threadIdx.x;
    const int warp = tid >> 5;
    const int lane = tid & 31;
    const int gid  = lane >> 2;       // 0..7
    const int tig  = lane & 3;        // 0..3
    const float* xb  = x    + (size_t)b * NFLAT;
    const float* k1b = g_k1 + (size_t)b * NFLAT;

    // one-time staging: W1f (tf32, zero-padded), w2s, bn scale/shift
    for (int i = tid; i < 176*104; i += 512) {
        const int k = i / 104, o = i - k * 104;
        const float w = (o < 81 && k < 162) ? __ldg(se_att_w1 + o*162 + k) : 0.f;
        W1f[i] = to_tf32(w);
    }
    for (int i = tid; i < 729; i += 512) w2s[i] = se_att_w2[i];
    if (tid < 81) {
        const float gam = se_att_bn[tid],       bet = se_att_bn[81 + tid];
        const float mea = se_att_bn[162 + tid], var = se_att_bn[243 + tid];
        const float s = gam * rsqrtf(var + EPSV);
        bnS[tid] = s; bnH[tid] = bet - mea * s;
    }

    // S^T chunk loader: 16 k-rows x 512 n-cols; thread = (kk = tid>>5, n0 = tid&31)
    const int kk = tid >> 5;
    const int n0 = tid & 31;
    float r[16];
    {   // prefetch chunk 0 (j = kk < 81 -> x)
        const float* row = xb + kk * 512;
        #pragma unroll
        for (int i = 0; i < 16; i++) r[i] = row[n0 + 32*i];
    }

    for (int pass = 0; pass < 2; pass++) {
        const int m0 = (warp + 16 * pass) << 4;    // channel base, 0..496

        float acc[11][4];
        #pragma unroll
        for (int nb = 0; nb < 11; nb++)
            #pragma unroll
            for (int e = 0; e < 4; e++) acc[nb][e] = 0.f;

        for (int kc = 0; kc < 11; kc++) {
            __syncthreads();      // prior compute done reading SH
            #pragma unroll
            for (int i = 0; i < 16; i++) {
                const int n = n0 + 32*i;
                SH[n*17 + kk] = to_tf32(r[i]);
            }
            __syncthreads();

            // prefetch next chunk (wraps to chunk 0 for pass 1)
            if (!(pass == 1 && kc == 10)) {
                const int nkc = (kc < 10) ? kc + 1 : 0;
                const int j = nkc * 16 + kk;
                if (j < 81) {
                    const float* row = xb + j * 512;
                    #pragma unroll
                    for (int i = 0; i < 16; i++) r[i] = row[n0 + 32*i];
                } else if (j < 162) {
                    const float* row = k1b + (j - 81) * 512;
                    #pragma unroll
                    for (int i = 0; i < 16; i++) r[i] = row[n0 + 32*i];
                } else {
                    #pragma unroll
                    for (int i = 0; i < 16; i++) r[i] = 0.f;
                }
            }

            // compute: 2 k8-steps over this chunk
            #pragma unroll
            for (int ks = 0; ks < 2; ks++) {
                const int kl = ks * 8 + tig;
                const int jr = kc * 16 + kl;
                const uint32_t a0 = __float_as_uint(SH[(m0+gid  )*17 + kl]);
                const uint32_t a1 = __float_as_uint(SH[(m0+gid+8)*17 + kl]);
                const uint32_t a2 = __float_as_uint(SH[(m0+gid  )*17 + kl + 4]);
                const uint32_t a3 = __float_as_uint(SH[(m0+gid+8)*17 + kl + 4]);
                const float* wr0 = W1f + (size_t)jr * 104;
                const float* wr1 = W1f + (size_t)(jr + 4) * 104;
                #pragma unroll
                for (int nb = 0; nb < 11; nb++) {
                    const uint32_t b0 = __float_as_uint(wr0[nb*8 + gid]);
                    const uint32_t b1 = __float_as_uint(wr1[nb*8 + gid]);
                    mma_tf32(acc[nb], a0, a1, a2, a3, b0, b1);
                }
            }
        }

        // register epilogue: bn+relu+w2 -> logits for channels m0+gid, m0+gid+8
        float lg[2][9];
        #pragma unroll
        for (int rr = 0; rr < 2; rr++)
            #pragma unroll
            for (int d = 0; d < 9; d++) lg[rr][d] = 0.f;
        #pragma unroll
        for (int nb = 0; nb < 11; nb++) {
            #pragma unroll
            for (int e = 0; e < 4; e++) {
                const int o = nb*8 + tig*2 + (e & 1);
                if (o < 81) {
                    const float a1v = fmaxf(fmaf(acc[nb][e], bnS[o], bnH[o]), 0.f);
                    const int rr = e >> 1;
                    #pragma unroll
                    for (int d = 0; d < 9; d++)
                        lg[rr][d] = fmaf(w2s[d*81 + o], a1v, lg[rr][d]);
                }
            }
        }
        #pragma unroll
        for (int rr = 0; rr < 2; rr++)
            #pragma unroll
            for (int d = 0; d < 9; d++) {
                lg[rr][d] += __shfl_xor_sync(0xffffffffu, lg[rr][d], 1);
                lg[rr][d] += __shfl_xor_sync(0xffffffffu, lg[rr][d], 2);
            }
        if (tig == 0) {
            #pragma unroll
            for (int d = 0; d < 9; d++) {
                const float bias = __ldg(se_att_b2 + d);
                a2s[d*512 + m0 + gid]     = lg[0][d] + bias;
                a2s[d*512 + m0 + gid + 8] = lg[1][d] + bias;
            }
        }
    }
    __syncthreads();

    // softmax over the 9 spectral taps, per column
    {
        const int n = tid;
        float v[9], mx = -1e30f;
        #pragma unroll
        for (int d = 0; d < 9; d++) { v[d] = a2s[d*512 + n]; mx = fmaxf(mx, v[d]); }
        float ssum = 0.f;
        #pragma unroll
        for (int d = 0; d < 9; d++) { v[d] = __expf(v[d] - mx); ssum += v[d]; }
        const float inv = 1.0f / ssum;
        #pragma unroll
        for (int d = 0; d < 9; d++) a2s[d*512 + n] = v[d] * inv;
    }
    __syncthreads();   // all SH reads long done; safe to overwrite with vsm

    // stage v band (rows = channels -4..515, zero-filled)
    {
        const float* vb = g_v + (size_t)b * NFLAT;
        for (int i = tid; i < 520 * NHW; i += 512) {
            const int g = i - 4 * NHW;
            vsm[i] = ((unsigned)g < (unsigned)NFLAT) ? vb[g] : 0.f;
        }
    }
    __syncthreads();

    // out += alpha * sum_d attn[d,ch] * v[ch+d-4, p]
    const float alpha = alpha_p[0];
    float* outb = out + (size_t)b * NFLAT;
    int ch = tid / 81;
    int p  = tid - ch * 81;
    for (int e = tid; e < NFLAT; e += 512) {
        float s = 0.f;
        #pragma unroll
        for (int d = 0; d < 9; d++)
            s = fmaf(a2s[d*512 + ch], vsm[(ch + d)*81 + p], s);
        outb[e] += alpha * s;
        p += 26; ch += 6;                 // advance by 512 = 6*81 + 26
        if (p >= 81) { p -= 81; ch += 1; }
    }
}

extern "C" void kernel_launch(void* const* d_in, const int* in_sizes, int n_in,
                              void* d_out, int out_size) {
    const float* x         = (const float*)d_in[0];
    const float* alpha     = (const float*)d_in[1];
    const float* sa_key_w  = (const float*)d_in[2];
    const float* sa_key_bn = (const float*)d_in[3];
    const float* sa_att_w1 = (const float*)d_in[4];
    const float* sa_att_bn = (const float*)d_in[5];
    const float* sa_att_w2 = (const float*)d_in[6];
    const float* sa_att_b2 = (const float*)d_in[7];
    const float* se_key_w  = (const float*)d_in[8];
    const float* se_key_b  = (const float*)d_in[9];
    const float* se_att_w1 = (const float*)d_in[10];
    const float* se_att_bn = (const float*)d_in[11];
    const float* se_att_w2 = (const float*)d_in[12];
    const float* se_att_b2 = (const float*)d_in[13];
    const float* se_val_w  = (const float*)d_in[14];
    const float* se_val_b  = (const float*)d_in[15];
    float* out = (float*)d_out;

    const int smemA = A_SMEM_FLOATS * 4;     // 68040 B
    const int smemB = B_SMEM_FLOATS * 4;     // 190476 B
    cudaFuncSetAttribute(dmuca_kernelA,
        cudaFuncAttributeMaxDynamicSharedMemorySize, smemA);
    cudaFuncSetAttribute(dmuca_kernelB,
        cudaFuncAttributeMaxDynamicSharedMemorySize, smemB);

    dmuca_kernelA<<<NB*8, 256, smemA>>>(x, alpha, sa_key_w, sa_key_bn,
                                        sa_att_w1, sa_att_bn, sa_att_w2, sa_att_b2,
                                        se_key_w, se_key_b, se_val_w, se_val_b, out);
    dmuca_kernelB<<<NB, 512, smemB>>>(x, alpha, se_att_w1, se_att_bn,
                                      se_att_w2, se_att_b2, out);
}

// round 11
// speedup vs baseline: 1.2772x; 1.0190x over previous
#include <cuda_runtime.h>
#include <cuda_bf16.h>
#include <cstdint>

#define NB    256
#define NC    512
#define NHW   81
#define NFLAT (NC*NHW)           // 41472 per batch
#define EPSV  1e-5f

__device__ __forceinline__ float to_tf32(float x) {
    float r; asm("cvt.rna.tf32.f32 %0, %1;" : "=f"(r) : "f"(x)); return r;
}
// m16n8k8 tf32 warp MMA (baseline PTX, sm_80+): D += A*B
__device__ __forceinline__ void mma_tf32(float c[4],
                                         uint32_t a0, uint32_t a1,
                                         uint32_t a2, uint32_t a3,
                                         uint32_t b0, uint32_t b1) {
    asm volatile("mma.sync.aligned.m16n8k8.row.col.f32.tf32.tf32.f32 "
                 "{%0,%1,%2,%3}, {%4,%5,%6,%7}, {%8,%9}, {%0,%1,%2,%3};"
                 : "+f"(c[0]), "+f"(c[1]), "+f"(c[2]), "+f"(c[3])
                 : "r"(a0), "r"(a1), "r"(a2), "r"(a3), "r"(b0), "r"(b1));
}
__device__ __forceinline__ void cp_async16(uint32_t s, const void* g) {
    asm volatile("cp.async.ca.shared.global [%0], [%1], 16;" :: "r"(s), "l"(g));
}
__device__ __forceinline__ void cp_commit() {
    asm volatile("cp.async.commit_group;");
}
template<int N>
__device__ __forceinline__ void cp_wait() {
    asm volatile("cp.async.wait_group %0;" :: "n"(N));
}

// Global scratch (allocation-free rule: __device__ arrays)
__device__ __align__(16) float g_k1[(size_t)NB * NFLAT];  // SeMCA key
__device__ __align__(16) float g_v [(size_t)NB * NFLAT];  // SeMCA value (dw3x3)

// ---------------------------------------------------------------------------
// Kernel A (banded): unchanged (passing since round 5).
// ---------------------------------------------------------------------------
#define A_SMEM_FLOATS (5832 + 729 + 81 + 8*1296)   // 17010

__global__ __launch_bounds__(256, 3)
void dmuca_kernelA(const float* __restrict__ x,
                   const float* __restrict__ alpha_p,
                   const float* __restrict__ sa_key_w,
                   const float* __restrict__ sa_key_bn,
                   const float* __restrict__ sa_att_w1,
                   const float* __restrict__ sa_att_bn,
                   const float* __restrict__ sa_att_w2,
                   const float* __restrict__ sa_att_b2,
                   const float* __restrict__ se_key_w,
                   const float* __restrict__ se_key_b,
                   const float* __restrict__ se_val_w,
                   const float* __restrict__ se_val_b,
                   float* __restrict__ out)
{
    extern __shared__ float sm[];
    float* Xs    = sm;
    float* sekw  = sm + 5832;
    float* sekb  = sekw + 729;
    float* stage = sekb + 81;

    const int bb   = blockIdx.x;
    const int b    = bb >> 3;
    const int band = bb & 7;
    const int chlo = band << 6;
    const int tid  = threadIdx.x;
    const int warp = tid >> 5;
    const int lane = tid & 31;
    const float* xb = x + (size_t)b * NFLAT;

    {
        const int gbase = (chlo - 4) * NHW;
        for (int i = tid; i < 5832; i += 256) {
            const int g = gbase + i;
            Xs[i] = ((unsigned)g < (unsigned)NFLAT) ? xb[g] : 0.f;
        }
        for (int i = tid; i < 729; i += 256) sekw[i] = se_key_w[i];
        if (tid < 81) sekb[tid] = se_key_b[tid];
    }
    __syncthreads();

    const float alpha = alpha_p[0];
    const float oma   = 1.0f - alpha;

    const int g_head = (chlo >> 3) + warp;
    const int chbase = chlo + warp * 8;
    float* ks   = stage + warp * 1296;
    float* k1st = ks + 648;

    #pragma unroll
    for (int l = 0; l < 8; l++) {
        const int ch = chbase + l;
        const int lr = warp*8 + l + 4;
        const float* Xc = Xs + lr * NHW;
        float wkv[9], wks[9];
        #pragma unroll
        for (int k = 0; k < 9; k++) wkv[k] = __ldg(se_val_w + ch*9 + k);
        #pragma unroll
        for (int k = 0; k < 9; k++) wks[k] = __ldg(sa_key_w + ch*9 + k);
        const float vbias = __ldg(se_val_b + ch);
        const float gam = __ldg(sa_key_bn + ch);
        const float bet = __ldg(sa_key_bn + 512 + ch);
        const float mea = __ldg(sa_key_bn + 1024 + ch);
        const float var = __ldg(sa_key_bn + 1536 + ch);
        const float s   = gam * rsqrtf(var + EPSV);
        const float sh  = bet - mea * s;

        float* gk = g_k1 + (size_t)b * NFLAT + ch * NHW;
        float* gv = g_v  + (size_t)b * NFLAT + ch * NHW;

        #pragma unroll
        for (int t = 0; t < 3; t++) {
            const int p = lane + 32 * t;
            if (p < 81) {
                float acc = sekb[p];
                #pragma unroll
                for (int d = 0; d < 9; d++)
                    acc = fmaf(sekw[p*9 + d], Xs[(lr - 4 + d)*NHW + p], acc);
                gk[p] = acc;
                k1st[l*81 + p] = acc;

                const int h = p / 9, w = p - h * 9;
                float va = vbias, sa = 0.f;
                #pragma unroll
                for (int kh = 0; kh < 3; kh++) {
                    const int hh = h + kh - 1;
                    if ((unsigned)hh < 9u) {
                        #pragma unroll
                        for (int kw = 0; kw < 3; kw++) {
                            const int ww = w + kw - 1;
                            if ((unsigned)ww < 9u) {
                                const float xv = Xc[hh*9 + ww];
                                va = fmaf(wkv[kh*3+kw], xv, va);
                                sa = fmaf(wks[kh*3+kw], xv, sa);
                            }
                        }
                    }
                }
                gv[p] = va;
                ks[l*81 + p] = fmaxf(fmaf(sa, s, sh), 0.f);
            }
        }
    }
    __syncwarp();

    const float bg = __ldg(sa_att_b2 + g_head);
    float a2b[3] = {bg, bg, bg};
    #pragma unroll
    for (int o = 0; o < 8; o++) {
        const int oc = chbase + o;
        float w1r[16];
        #pragma unroll
        for (int i = 0; i < 16; i++) w1r[i] = __ldg(sa_att_w1 + oc*16 + i);
        const float gam = __ldg(sa_att_bn + oc);
        const float bet = __ldg(sa_att_bn + 512 + oc);
        const float mea = __ldg(sa_att_bn + 1024 + oc);
        const float var = __ldg(sa_att_bn + 1536 + oc);
        const float s2  = gam * rsqrtf(var + EPSV);
        const float sh2 = bet - mea * s2;
        const float w2v = __ldg(sa_att_w2 + oc);
        #pragma unroll
        for (int t = 0; t < 3; t++) {
            const int pp = lane + 32 * t;
            if (pp < 81) {
                float aa = 0.f;
                #pragma unroll
                for (int l = 0; l < 8; l++) {
                    aa = fmaf(w1r[2*l],   ks[l*81 + pp], aa);
                    aa = fmaf(w1r[2*l+1], Xs[(warp*8 + l + 4)*NHW + pp], aa);
                }
                aa = fmaxf(fmaf(aa, s2, sh2), 0.f);
                a2b[t] = fmaf(w2v, aa, a2b[t]);
            }
        }
    }

    float m = -1e30f;
    #pragma unroll
    for (int t = 0; t < 3; t++) { if (lane + 32*t < 81) m = fmaxf(m, a2b[t]); }
    #pragma unroll
    for (int off = 16; off > 0; off >>= 1)
        m = fmaxf(m, __shfl_xor_sync(0xffffffffu, m, off));
    float ex[3] = {0.f, 0.f, 0.f};
    float ssum = 0.f;
    #pragma unroll
    for (int t = 0; t < 3; t++) {
        const int pp = lane + 32 * t;
        if (pp < 81) { ex[t] = __expf(a2b[t] - m); ssum += ex[t]; }
    }
    #pragma unroll
    for (int off = 16; off > 0; off >>= 1)
        ssum += __shfl_xor_sync(0xffffffffu, ssum, off);
    const float inv = 1.0f / ssum;

    #pragma unroll
    for (int t = 0; t < 3; t++) {
        const int pp = lane + 32 * t;
        if (pp < 81) {
            const float att = ex[t] * inv;
            #pragma unroll
            for (int l = 0; l < 8; l++) {
                const int ch = chbase + l;
                const float o2 = ks[l*81 + pp]
                               + att * Xs[(warp*8 + l + 4)*NHW + pp];
                out[(size_t)b * NFLAT + ch*NHW + pp]
                    = oma * o2 + alpha * k1st[l*81 + pp];
            }
        }
    }
}

// ---------------------------------------------------------------------------
// Kernel B (warp-MMA tf32, cp.async staging): grid = NB, 512 threads.
// C^T[512,88] = S^T[512,176] @ W1^T[176,88]; S = [x rows 0..80 | k1 81..161].
// S chunks staged UNTRANSPOSED [k=16][n=512 (stride 520)] via double-buffered
// cp.async; raw f32 fed to mma.tf32 (HW truncation; round-9/10 validated the
// precision margin). W1f tf32 (rna, one-time). 2 passes (warp = m16 x n88);
// logits (bn+relu+w2) in the register epilogue; softmax + v-band + out.
//
// smem floats: SH2[2*16*520=16640]@0 | W1f[176*104=18304]@16640 (ends 34944)
//   vsm alias @0 (520*81=42120) | a2s@42120 (4608) | w2s@46728 (729)
//   bnS@47457 (81) | bnH@47538 (81)   total 47619 fl = 190476 B
// ---------------------------------------------------------------------------
#define FB_SH   0
#define FB_W1F  16640
#define FB_A2S  42120
#define FB_W2   46728
#define FB_BNS  47457
#define FB_BNH  47538
#define B_SMEM_FLOATS 47619
#define SH_STRIDE 520

__global__ __launch_bounds__(512, 1)
void dmuca_kernelB(const float* __restrict__ x,
                   const float* __restrict__ alpha_p,
                   const float* __restrict__ se_att_w1,
                   const float* __restrict__ se_att_bn,
                   const float* __restrict__ se_att_w2,
                   const float* __restrict__ se_att_b2,
                   float* __restrict__ out)
{
    extern __shared__ float sm[];
    float* SH2 = sm + FB_SH;    // 2 x [16][520] raw f32 chunks of S
    float* W1f = sm + FB_W1F;   // [j=176][o pad 104] tf32
    float* vsm = sm;            // epilogue alias, 520*81
    float* a2s = sm + FB_A2S;
    float* w2s = sm + FB_W2;
    float* bnS = sm + FB_BNS;
    float* bnH = sm + FB_BNH;

    const int b    = blockIdx.x;
    const int tid  = threadIdx.x;
    const int warp = tid >> 5;
    const int lane = tid & 31;
    const int gid  = lane >> 2;       // 0..7
    const int tig  = lane & 3;        // 0..3
    const float* xb  = x    + (size_t)b * NFLAT;
    const float* k1b = g_k1 + (size_t)b * NFLAT;

    const uint32_t sh_base = (uint32_t)__cvta_generic_to_shared(SH2);

    // one-time staging: W1f (tf32, zero-padded), w2s, bn scale/shift
    for (int i = tid; i < 176*104; i += 512) {
        const int k = i / 104, o = i - k * 104;
        const float w = (o < 81 && k < 162) ? __ldg(se_att_w1 + o*162 + k) : 0.f;
        W1f[i] = to_tf32(w);
    }
    for (int i = tid; i < 729; i += 512) w2s[i] = se_att_w2[i];
    if (tid < 81) {
        const float gam = se_att_bn[tid],       bet = se_att_bn[81 + tid];
        const float mea = se_att_bn[162 + tid], var = se_att_bn[243 + tid];
        const float s = gam * rsqrtf(var + EPSV);
        bnS[tid] = s; bnH[tid] = bet - mea * s;
    }

    // stage chunk c (k rows c*16..c*16+15) into buffer `buf` via cp.async
    auto stage_chunk = [&](int c, int buf) {
        const uint32_t boff = (uint32_t)(buf * 16 * SH_STRIDE * 4);
        #pragma unroll
        for (int q = 0; q < 4; q++) {
            const int f4 = q * 512 + tid;          // 0..2047
            const int kk = f4 >> 7, c4 = f4 & 127; // 128 float4 per 512-f row
            const int j  = c * 16 + kk;
            const uint32_t dst = sh_base + boff
                               + (uint32_t)((kk * SH_STRIDE + c4 * 4) * 4);
            if (j < 81) {
                cp_async16(dst, (const void*)(xb + j*512 + c4*4));
            } else if (j < 162) {
                cp_async16(dst, (const void*)(k1b + (j-81)*512 + c4*4));
            } else {
                float4 z = {0.f, 0.f, 0.f, 0.f};
                *(float4*)(SH2 + buf*16*SH_STRIDE + kk*SH_STRIDE + c4*4) = z;
            }
        }
        cp_commit();
    };

    stage_chunk(0, 0);

    for (int pass = 0; pass < 2; pass++) {
        const int m0 = (warp + 16 * pass) << 4;    // channel base

        float acc[11][4];
        #pragma unroll
        for (int nb = 0; nb < 11; nb++)
            #pragma unroll
            for (int e = 0; e < 4; e++) acc[nb][e] = 0.f;

        for (int kc = 0; kc < 11; kc++) {
            const int gi = pass * 11 + kc;
            if (gi < 21) { stage_chunk((gi + 1) % 11, (gi + 1) & 1); cp_wait<1>(); }
            else         { cp_wait<0>(); }
            __syncthreads();

            const float* sb = SH2 + (gi & 1) * 16 * SH_STRIDE;
            #pragma unroll
            for (int ks = 0; ks < 2; ks++) {
                const int kl = ks * 8 + tig;
                const int jr = kc * 16 + kl;
                const uint32_t a0 = __float_as_uint(sb[ kl     *SH_STRIDE + m0 + gid]);
                const uint32_t a1 = __float_as_uint(sb[ kl     *SH_STRIDE + m0 + gid + 8]);
                const uint32_t a2 = __float_as_uint(sb[(kl + 4)*SH_STRIDE + m0 + gid]);
                const uint32_t a3 = __float_as_uint(sb[(kl + 4)*SH_STRIDE + m0 + gid + 8]);
                const float* wr0 = W1f + (size_t)jr * 104;
                const float* wr1 = W1f + (size_t)(jr + 4) * 104;
                #pragma unroll
                for (int nb = 0; nb < 11; nb++) {
                    const uint32_t b0 = __float_as_uint(wr0[nb*8 + gid]);
                    const uint32_t b1 = __float_as_uint(wr1[nb*8 + gid]);
                    mma_tf32(acc[nb], a0, a1, a2, a3, b0, b1);
                }
            }
            __syncthreads();
        }

        // register epilogue: bn+relu+w2 -> logits for channels m0+gid, m0+gid+8
        float lg[2][9];
        #pragma unroll
        for (int rr = 0; rr < 2; rr++)
            #pragma unroll
            for (int d = 0; d < 9; d++) lg[rr][d] = 0.f;
        #pragma unroll
        for (int nb = 0; nb < 11; nb++) {
            #pragma unroll
            for (int e = 0; e < 4; e++) {
                const int o = nb*8 + tig*2 + (e & 1);
                if (o < 81) {
                    const float a1v = fmaxf(fmaf(acc[nb][e], bnS[o], bnH[o]), 0.f);
                    const int rr = e >> 1;
                    #pragma unroll
                    for (int d = 0; d < 9; d++)
                        lg[rr][d] = fmaf(w2s[d*81 + o], a1v, lg[rr][d]);
                }
            }
        }
        #pragma unroll
        for (int rr = 0; rr < 2; rr++)
            #pragma unroll
            for (int d = 0; d < 9; d++) {
                lg[rr][d] += __shfl_xor_sync(0xffffffffu, lg[rr][d], 1);
                lg[rr][d] += __shfl_xor_sync(0xffffffffu, lg[rr][d], 2);
            }
        if (tig == 0) {
            #pragma unroll
            for (int d = 0; d < 9; d++) {
                const float bias = __ldg(se_att_b2 + d);
                a2s[d*512 + m0 + gid]     = lg[0][d] + bias;
                a2s[d*512 + m0 + gid + 8] = lg[1][d] + bias;
            }
        }
    }
    __syncthreads();

    // softmax over the 9 spectral taps, per column
    {
        const int n = tid;
        float v[9], mx = -1e30f;
        #pragma unroll
        for (int d = 0; d < 9; d++) { v[d] = a2s[d*512 + n]; mx = fmaxf(mx, v[d]); }
        float ssum = 0.f;
        #pragma unroll
        for (int d = 0; d < 9; d++) { v[d] = __expf(v[d] - mx); ssum += v[d]; }
        const float inv = 1.0f / ssum;
        #pragma unroll
        for (int d = 0; d < 9; d++) a2s[d*512 + n] = v[d] * inv;
    }
    __syncthreads();   // all SH2 reads long done; safe to overwrite with vsm

    // stage v band (rows = channels -4..515, zero-filled)
    {
        const float* vb = g_v + (size_t)b * NFLAT;
        for (int i = tid; i < 520 * NHW; i += 512) {
            const int g = i - 4 * NHW;
            vsm[i] = ((unsigned)g < (unsigned)NFLAT) ? vb[g] : 0.f;
        }
    }
    __syncthreads();

    // out += alpha * sum_d attn[d,ch] * v[ch+d-4, p]
    const float alpha = alpha_p[0];
    float* outb = out + (size_t)b * NFLAT;
    int ch = tid / 81;
    int p  = tid - ch * 81;
    for (int e = tid; e < NFLAT; e += 512) {
        float s = 0.f;
        #pragma unroll
        for (int d = 0; d < 9; d++)
            s = fmaf(a2s[d*512 + ch], vsm[(ch + d)*81 + p], s);
        outb[e] += alpha * s;
        p += 26; ch += 6;                 // advance by 512 = 6*81 + 26
        if (p >= 81) { p -= 81; ch += 1; }
    }
}

extern "C" void kernel_launch(void* const* d_in, const int* in_sizes, int n_in,
                              void* d_out, int out_size) {
    const float* x         = (const float*)d_in[0];
    const float* alpha     = (const float*)d_in[1];
    const float* sa_key_w  = (const float*)d_in[2];
    const float* sa_key_bn = (const float*)d_in[3];
    const float* sa_att_w1 = (const float*)d_in[4];
    const float* sa_att_bn = (const float*)d_in[5];
    const float* sa_att_w2 = (const float*)d_in[6];
    const float* sa_att_b2 = (const float*)d_in[7];
    const float* se_key_w  = (const float*)d_in[8];
    const float* se_key_b  = (const float*)d_in[9];
    const float* se_att_w1 = (const float*)d_in[10];
    const float* se_att_bn = (const float*)d_in[11];
    const float* se_att_w2 = (const float*)d_in[12];
    const float* se_att_b2 = (const float*)d_in[13];
    const float* se_val_w  = (const float*)d_in[14];
    const float* se_val_b  = (const float*)d_in[15];
    float* out = (float*)d_out;

    const int smemA = A_SMEM_FLOATS * 4;     // 68040 B
    const int smemB = B_SMEM_FLOATS * 4;     // 190476 B
    cudaFuncSetAttribute(dmuca_kernelA,
        cudaFuncAttributeMaxDynamicSharedMemorySize, smemA);
    cudaFuncSetAttribute(dmuca_kernelB,
        cudaFuncAttributeMaxDynamicSharedMemorySize, smemB);

    dmuca_kernelA<<<NB*8, 256, smemA>>>(x, alpha, sa_key_w, sa_key_bn,
                                        sa_att_w1, sa_att_bn, sa_att_w2, sa_att_b2,
                                        se_key_w, se_key_b, se_val_w, se_val_b, out);
    dmuca_kernelB<<<NB, 512, smemB>>>(x, alpha, se_att_w1, se_att_bn,
                                      se_att_w2, se_att_b2, out);
}